// round 3
// baseline (speedup 1.0000x reference)
#include <cuda_runtime.h>

#define XSIZE 256
#define NB 128

__global__ __launch_bounds__(128) void qconv_kernel3(const float* __restrict__ x,
                                                     const float* __restrict__ w,
                                                     float* __restrict__ out)
{
    const int j  = threadIdx.x;      // col block 0..127
    const int bi = blockIdx.x;       // b*128 + i
    const int i  = bi & (NB - 1);
    const size_t base = ((size_t)(bi >> 7) * XSIZE + 2 * i) * XSIZE + 2 * j;
    const float2 r0 = *reinterpret_cast<const float2*>(x + base);
    const float2 r1 = *reinterpret_cast<const float2*>(x + base + XSIZE);
    const float x0 = r0.x, x1 = r0.y, x2 = r1.x, x3 = r1.y;

    // RX layer: tangent form. tau_q = tan(w_q/2); overall factor C = prod cos(w_q/2)
    // is folded into the final probability scale (C^2 * 0.0625).
    float tau[4], ntau[4];
    float C = 1.0f;
#pragma unroll
    for (int q = 0; q < 4; q++) {
        float cq, sq;
        __sincosf(0.5f * __ldg(w + q), &sq, &cq);
        tau[q]  = __fdividef(sq, cq);
        ntau[q] = -tau[q];
        C *= cq;
    }
    const float scale = 0.0625f * C * C;

    const float S  = x0 * x0 + x1 * x1 + x2 * x2 + x3 * x3;
    const float S4 = 0.25f * S;

    // t_e = x3 + (e&4?+:-)x2 + (e&2?+:-)x1 + (e&1?+:-)x0 via Gray-code chain
    const float dx0 = 2.0f * x0, dx1 = 2.0f * x1, dx2 = 2.0f * x2;
    float t[8];
    t[0] = x3 - x2 - x1 - x0;
    t[1] = t[0] + dx0;
    t[3] = t[1] + dx1;
    t[2] = t[3] - dx0;
    t[6] = t[2] + dx2;
    t[7] = t[6] + dx0;
    t[5] = t[7] - dx1;
    t[4] = t[5] - dx0;

    // diag_k = exp(i*phi), phi = 0.25*(S - t^2) -/+ 0.5*t; t_{k^15} = -t_k
    float vr[16], vi[16];
#pragma unroll
    for (int e = 0; e < 8; e++) {
        const float te = t[e];
        const float u  = __fmaf_rn(-0.25f * te, te, S4);
        const float p1 = __fmaf_rn(-0.5f, te, u);
        const float p0 = __fmaf_rn( 0.5f, te, u);
        const int k1 = 8 | e;
        const int k0 = e ^ 7;
        __sincosf(p1, &vi[k1], &vr[k1]);
        __sincosf(p0, &vi[k0], &vr[k0]);
    }

    // RX butterflies in tangent form: 4 fmas per butterfly.
    // a' = a + tau*b_i ; a_i' = a_i - tau*b ; b' = b + tau*a_i ; b_i' = b_i - tau*a
#pragma unroll
    for (int q = 0; q < 4; q++) {
        const float tq = tau[q], nq = ntau[q];
#pragma unroll
        for (int m = 0; m < 8; m++) {
            const int j0 = ((m >> q) << (q + 1)) | (m & ((1 << q) - 1));
            const int j1 = j0 | (1 << q);
            const float ar = vr[j0], ai = vi[j0];
            const float br = vr[j1], bim = vi[j1];
            vr[j0] = __fmaf_rn(tq, bim, ar);
            vi[j0] = __fmaf_rn(nq, br,  ai);
            vr[j1] = __fmaf_rn(tq, ai,  br);
            vi[j1] = __fmaf_rn(nq, ar,  bim);
        }
    }

    // CNOT ring + per-qubit readout = parity-masked probability sums.
    float o0 = 0.f, o1 = 0.f, o2 = 0.f, o3 = 0.f;
#pragma unroll
    for (int k = 0; k < 16; k++) {
        const float p = __fmaf_rn(vr[k], vr[k], vi[k] * vi[k]);
        if (__popc(k & 0xF) & 1) o0 += p;
        if (__popc(k & 0x7) & 1) o1 += p;
        if (__popc(k & 0x3) & 1) o2 += p;
        if (__popc(k & 0xE) & 1) o3 += p;
    }

    float4 o;
    o.x = scale * o0;
    o.y = scale * o1;
    o.z = scale * o2;
    o.w = scale * o3;
    reinterpret_cast<float4*>(out)[(size_t)bi * NB + j] = o;
}

extern "C" void kernel_launch(void* const* d_in, const int* in_sizes, int n_in,
                              void* d_out, int out_size)
{
    const float* x = (const float*)d_in[0];
    const float* w = (const float*)d_in[1];
    float* out = (float*)d_out;
    const int batch = in_sizes[0] / (XSIZE * XSIZE);
    qconv_kernel3<<<batch * NB, NB>>>(x, w, out);
}

// round 4
// speedup vs baseline: 1.0225x; 1.0225x over previous
#include <cuda_runtime.h>

#define XSIZE 256
#define NB 128

__global__ __launch_bounds__(128) void qconv_kernel4(const float* __restrict__ x,
                                                     const float* __restrict__ w,
                                                     float* __restrict__ out)
{
    __shared__ float sh[5];   // tau0..tau3, scale

    // Uniform weight math computed once per block (saves 12 MUFU ops/thread).
    if (threadIdx.x == 0) {
        float C = 1.0f;
#pragma unroll
        for (int q = 0; q < 4; q++) {
            float cq, sq;
            __sincosf(0.5f * __ldg(w + q), &sq, &cq);
            sh[q] = __fdividef(sq, cq);    // tan(w_q/2)
            C *= cq;
        }
        sh[4] = 0.0625f * C * C;           // fold prod cos^2 into prob scale
    }

    const int j  = threadIdx.x;
    const int bi = blockIdx.x;             // b*128 + i
    const int i  = bi & (NB - 1);
    const size_t base = ((size_t)(bi >> 7) * XSIZE + 2 * i) * XSIZE + 2 * j;
    const float2 r0 = *reinterpret_cast<const float2*>(x + base);
    const float2 r1 = *reinterpret_cast<const float2*>(x + base + XSIZE);
    const float x0 = r0.x, x1 = r0.y, x2 = r1.x, x3 = r1.y;

    const float S4 = 0.25f * (x0 * x0 + x1 * x1 + x2 * x2 + x3 * x3);
    const float dx0 = 2.0f * x0, dx1 = 2.0f * x1, dx2 = 2.0f * x2;

    // Rotors for Gray-code construction of T_e = exp(i * t_e / 2):
    // a Gray step flips sign of x_q in t_e (delta 2*x_q) -> T *= exp(+-i*x_q).
    float c0, s0, c1, s1, c2, s2;
    __sincosf(x0, &s0, &c0);
    __sincosf(x1, &s1, &c1);
    __sincosf(x2, &s2, &c2);

    float tcur = x3 - x2 - x1 - x0;        // t_0
    float Tr, Ti;
    __sincosf(0.5f * tcur, &Ti, &Tr);      // T = exp(i*t_0/2)

    float vr[16], vi[16];

    // diag entries for index pair (8|e, e^7):
    //   p1 = u - t/2 -> E*conj(T),  p0 = u + t/2 -> E*T,  E = exp(i*u)
#define EMIT(E_IDX)                                                         \
    {                                                                       \
        const float u = __fmaf_rn(-0.25f * tcur, tcur, S4);                 \
        float su, cu;                                                       \
        __sincosf(u, &su, &cu);                                             \
        const float a = cu * Tr, b = su * Ti, c = su * Tr, d = cu * Ti;     \
        vr[8 | (E_IDX)] = a + b;  vi[8 | (E_IDX)] = c - d;                  \
        vr[(E_IDX) ^ 7] = a - b;  vi[(E_IDX) ^ 7] = c + d;                  \
    }
    // T *= exp(i*sgn*x_q) with rotor (cq, sq)
#define STEP(CQ, SQ)                                                        \
    {                                                                       \
        const float nr = __fmaf_rn(Tr, (CQ), -Ti * (SQ));                   \
        Ti = __fmaf_rn(Tr, (SQ), Ti * (CQ));                                \
        Tr = nr;                                                            \
    }

    EMIT(0);
    tcur += dx0; STEP(c0,  s0); EMIT(1);
    tcur += dx1; STEP(c1,  s1); EMIT(3);
    tcur -= dx0; STEP(c0, -s0); EMIT(2);
    tcur += dx2; STEP(c2,  s2); EMIT(6);
    tcur += dx0; STEP(c0,  s0); EMIT(7);
    tcur -= dx1; STEP(c1, -s1); EMIT(5);
    tcur -= dx0; STEP(c0, -s0); EMIT(4);
#undef EMIT
#undef STEP

    __syncthreads();
    const float tau0 = sh[0], tau1 = sh[1], tau2 = sh[2], tau3 = sh[3];
    const float scale = sh[4];
    const float tau[4] = {tau0, tau1, tau2, tau3};

    // RX butterflies, tangent form (4 fma each); global cos factor folded in scale.
#pragma unroll
    for (int q = 0; q < 4; q++) {
        const float tq = tau[q];
#pragma unroll
        for (int m = 0; m < 8; m++) {
            const int j0 = ((m >> q) << (q + 1)) | (m & ((1 << q) - 1));
            const int j1 = j0 | (1 << q);
            const float ar = vr[j0], ai = vi[j0];
            const float br = vr[j1], bim = vi[j1];
            vr[j0] = __fmaf_rn( tq, bim, ar);
            vi[j0] = __fmaf_rn(-tq, br,  ai);
            vr[j1] = __fmaf_rn( tq, ai,  br);
            vi[j1] = __fmaf_rn(-tq, ar,  bim);
        }
    }

    // CNOT ring + per-qubit Z readout = parity-masked probability sums.
    float o0 = 0.f, o1 = 0.f, o2 = 0.f, o3 = 0.f;
#pragma unroll
    for (int k = 0; k < 16; k++) {
        const float p = __fmaf_rn(vr[k], vr[k], vi[k] * vi[k]);
        if (__popc(k & 0xF) & 1) o0 += p;
        if (__popc(k & 0x7) & 1) o1 += p;
        if (__popc(k & 0x3) & 1) o2 += p;
        if (__popc(k & 0xE) & 1) o3 += p;
    }

    float4 o;
    o.x = scale * o0;
    o.y = scale * o1;
    o.z = scale * o2;
    o.w = scale * o3;
    reinterpret_cast<float4*>(out)[(size_t)bi * NB + j] = o;
}

extern "C" void kernel_launch(void* const* d_in, const int* in_sizes, int n_in,
                              void* d_out, int out_size)
{
    const float* x = (const float*)d_in[0];
    const float* w = (const float*)d_in[1];
    float* out = (float*)d_out;
    const int batch = in_sizes[0] / (XSIZE * XSIZE);
    qconv_kernel4<<<batch * NB, NB>>>(x, w, out);
}

// round 7
// speedup vs baseline: 1.1193x; 1.0947x over previous
#include <cuda_runtime.h>

#define XSIZE 256

// One 2x2-patch quantum circuit: returns the 4 per-qubit expectations * scale.
__device__ __forceinline__ float4 qpatch(float x0, float x1, float x2, float x3,
                                         float tau0, float tau1, float tau2, float tau3,
                                         float scale)
{
    const float S4 = 0.25f * (x0 * x0 + x1 * x1 + x2 * x2 + x3 * x3);
    const float dx0 = 2.0f * x0, dx1 = 2.0f * x1, dx2 = 2.0f * x2;

    // Rotors: Gray step flips sign of x_q in t (delta 2 x_q) -> T *= exp(+-i x_q)
    float c0, s0, c1, s1, c2, s2;
    __sincosf(x0, &s0, &c0);
    __sincosf(x1, &s1, &c1);
    __sincosf(x2, &s2, &c2);

    float tcur = x3 - x2 - x1 - x0;          // t_0
    float Tr, Ti;
    __sincosf(0.5f * tcur, &Ti, &Tr);        // T = exp(i t_0 / 2)

    float vr[16], vi[16];

    // diag pair (8|e, e^7): p = u -/+ t/2 with E = exp(i u), u = S4 - t^2/4
#define EMIT(E_IDX)                                                         \
    {                                                                       \
        const float u = __fmaf_rn(-0.25f * tcur, tcur, S4);                 \
        float su, cu;                                                       \
        __sincosf(u, &su, &cu);                                             \
        const float a = cu * Tr, b = su * Ti, c = su * Tr, d = cu * Ti;     \
        vr[8 | (E_IDX)] = a + b;  vi[8 | (E_IDX)] = c - d;                  \
        vr[(E_IDX) ^ 7] = a - b;  vi[(E_IDX) ^ 7] = c + d;                  \
    }
#define STEP(CQ, SQ)                                                        \
    {                                                                       \
        const float nr = __fmaf_rn(Tr, (CQ), -Ti * (SQ));                   \
        Ti = __fmaf_rn(Tr, (SQ), Ti * (CQ));                                \
        Tr = nr;                                                            \
    }

    EMIT(0);
    tcur += dx0; STEP(c0,  s0); EMIT(1);
    tcur += dx1; STEP(c1,  s1); EMIT(3);
    tcur -= dx0; STEP(c0, -s0); EMIT(2);
    tcur += dx2; STEP(c2,  s2); EMIT(6);
    tcur += dx0; STEP(c0,  s0); EMIT(7);
    tcur -= dx1; STEP(c1, -s1); EMIT(5);
    tcur -= dx0; STEP(c0, -s0); EMIT(4);
#undef EMIT
#undef STEP

    // RX butterflies, tangent form (4 fma each); cos factors folded into scale.
    const float tau[4] = {tau0, tau1, tau2, tau3};
#pragma unroll
    for (int q = 0; q < 4; q++) {
        const float tq = tau[q];
#pragma unroll
        for (int m = 0; m < 8; m++) {
            const int j0 = ((m >> q) << (q + 1)) | (m & ((1 << q) - 1));
            const int j1 = j0 | (1 << q);
            const float ar = vr[j0], ai = vi[j0];
            const float br = vr[j1], bim = vi[j1];
            vr[j0] = __fmaf_rn( tq, bim, ar);
            vi[j0] = __fmaf_rn(-tq, br,  ai);
            vr[j1] = __fmaf_rn( tq, ai,  br);
            vi[j1] = __fmaf_rn(-tq, ar,  bim);
        }
    }

    // CNOT ring + per-qubit Z readout = parity-masked probability sums.
    float o0 = 0.f, o1 = 0.f, o2 = 0.f, o3 = 0.f;
#pragma unroll
    for (int k = 0; k < 16; k++) {
        const float p = __fmaf_rn(vr[k], vr[k], vi[k] * vi[k]);
        if (__popc(k & 0xF) & 1) o0 += p;
        if (__popc(k & 0x7) & 1) o1 += p;
        if (__popc(k & 0x3) & 1) o2 += p;
        if (__popc(k & 0xE) & 1) o3 += p;
    }

    float4 o;
    o.x = scale * o0;
    o.y = scale * o1;
    o.z = scale * o2;
    o.w = scale * o3;
    return o;
}

// 64 threads/block, TWO independent scalar patch streams per thread.
__global__ __launch_bounds__(64) void qconv_kernel5(const float* __restrict__ x,
                                                    const float* __restrict__ w,
                                                    float* __restrict__ out)
{
    __shared__ float sh[5];   // tau0..3, scale
    if (threadIdx.x == 0) {
        float C = 1.0f;
#pragma unroll
        for (int q = 0; q < 4; q++) {
            float cq, sq;
            __sincosf(0.5f * __ldg(w + q), &sq, &cq);
            sh[q] = __fdividef(sq, cq);
            C *= cq;
        }
        sh[4] = 0.0625f * C * C;
    }
    __syncthreads();
    const float tau0 = sh[0], tau1 = sh[1], tau2 = sh[2], tau3 = sh[3];
    const float scale = sh[4];

    const int t  = threadIdx.x;          // 0..63 -> patch pair
    const int bi = blockIdx.x;           // b*128 + i
    const int i  = bi & 127;
    const size_t base = ((size_t)(bi >> 7) * XSIZE + 2 * i) * XSIZE + 4 * t;
    const float4 r0 = *reinterpret_cast<const float4*>(x + base);
    const float4 r1 = *reinterpret_cast<const float4*>(x + base + XSIZE);

    // Two independent streams -> ptxas interleaves MUFU of B with FMA of A.
    const float4 oa = qpatch(r0.x, r0.y, r1.x, r1.y, tau0, tau1, tau2, tau3, scale);
    const float4 ob = qpatch(r0.z, r0.w, r1.z, r1.w, tau0, tau1, tau2, tau3, scale);

    float* dst = out + (size_t)bi * 512 + 8 * t;
    reinterpret_cast<float4*>(dst)[0] = oa;
    reinterpret_cast<float4*>(dst)[1] = ob;
}

extern "C" void kernel_launch(void* const* d_in, const int* in_sizes, int n_in,
                              void* d_out, int out_size)
{
    const float* x = (const float*)d_in[0];
    const float* w = (const float*)d_in[1];
    float* out = (float*)d_out;
    const int batch = in_sizes[0] / (XSIZE * XSIZE);
    qconv_kernel5<<<batch * 128, 64>>>(x, w, out);
}